// round 2
// baseline (speedup 1.0000x reference)
#include <cuda_runtime.h>
#include <cuda_bf16.h>
#include <math.h>

// Problem constants
constexpr int B   = 2;
constexpr int S   = 2048;
constexpr int E   = 1024;
constexpr int H   = 16;
constexpr int DH  = 64;          // head dim
constexpr int MLP = 4096;
constexpr int M   = B * S;       // 4096 rows
constexpr float SCALE = 0.125f;  // 1/sqrt(64)

// ---------------------------------------------------------------------------
// Scratch buffers (device globals; no allocation allowed)
// ---------------------------------------------------------------------------
__device__ float g_h1 [M * E];        // LN1 output
__device__ float g_qkv[M * 3 * E];    // QKV projection
__device__ float g_ctx[M * E];        // attention context
__device__ float g_att[M * E];        // out-proj + residual
__device__ float g_h2 [M * E];        // LN2 output
__device__ float g_m1 [M * MLP];      // MLP hidden
__device__ unsigned char g_mask[S * S]; // canonical uint8 mask
__device__ int g_mask_sz;             // detected element size of input mask

// ---------------------------------------------------------------------------
// Mask dtype detection + canonicalization.
// The reference mask is jnp bool; the harness may marshal it as bool(1B),
// bf16(2B), int32/float32(4B). Detect element size from raw byte patterns
// (values are only 0/1 logically):
//   bool : bytes 0/1 at every position -> byte==1 seen at p%4!=0
//   bf16 : 1.0 = [0x80,0x3F]           -> 0x3F seen at p%4==1
//   f32  : 1.0 = [0,0,0x80,0x3F]       -> neither of the above
//   int32: 1   = [1,0,0,0]             -> neither of the above
// For decode only SIZE matters: element nonzero <=> any of its bytes nonzero.
// ---------------------------------------------------------------------------
__global__ void mask_detect_kernel(const unsigned char* __restrict__ m)
{
    if (threadIdx.x == 0 && blockIdx.x == 0) {
        bool is1 = false, is2 = false;
        for (int p = 0; p < 8192; p++) {
            unsigned char v = m[p];
            if (v == 1u    && (p & 3) != 0) is1 = true;
            if (v == 0x3Fu && (p & 3) == 1) is2 = true;
        }
        g_mask_sz = is1 ? 1 : (is2 ? 2 : 4);
    }
}

__global__ __launch_bounds__(256) void mask_convert_kernel(
    const unsigned char* __restrict__ m, unsigned char* __restrict__ out)
{
    const int idx = blockIdx.x * 256 + threadIdx.x;   // element index
    const int sz = g_mask_sz;
    unsigned char nz = 0;
    const unsigned char* p = m + (size_t)idx * sz;
    for (int i = 0; i < sz; i++) nz |= p[i];
    out[idx] = nz ? 1 : 0;
}

// ---------------------------------------------------------------------------
// LayerNorm: one block per row, 256 threads, 4 elems/thread (E = 1024)
// ---------------------------------------------------------------------------
__global__ __launch_bounds__(256) void ln_kernel(
    const float* __restrict__ in, const float* __restrict__ g,
    const float* __restrict__ beta, float* __restrict__ out)
{
    __shared__ float sred[256];
    const int tid = threadIdx.x;
    const size_t row = blockIdx.x;
    const float* x = in + row * E;

    float v[4];
    float s = 0.f;
#pragma unroll
    for (int i = 0; i < 4; i++) { v[i] = x[tid + i * 256]; s += v[i]; }

    sred[tid] = s; __syncthreads();
#pragma unroll
    for (int off = 128; off > 0; off >>= 1) {
        if (tid < off) sred[tid] += sred[tid + off];
        __syncthreads();
    }
    const float mu = sred[0] * (1.f / E);
    __syncthreads();

    float sq = 0.f;
#pragma unroll
    for (int i = 0; i < 4; i++) { float d = v[i] - mu; sq += d * d; }
    sred[tid] = sq; __syncthreads();
#pragma unroll
    for (int off = 128; off > 0; off >>= 1) {
        if (tid < off) sred[tid] += sred[tid + off];
        __syncthreads();
    }
    const float rstd = rsqrtf(sred[0] * (1.f / E) + 1e-5f);

#pragma unroll
    for (int i = 0; i < 4; i++) {
        int c = tid + i * 256;
        out[row * E + c] = (v[i] - mu) * rstd * g[c] + beta[c];
    }
}

// ---------------------------------------------------------------------------
// SGEMM: C[M,N] = A[M,K] * W[N,K]^T + bias[N] (+ R[M,N] residual)
// Tiles: 128x128x16, 256 threads, 8x8 per thread.
// ---------------------------------------------------------------------------
constexpr int BMT = 128, BNT = 128, BKT_G = 16;

template <bool RES>
__global__ __launch_bounds__(256) void gemm_kernel(
    const float* __restrict__ A, const float* __restrict__ W,
    const float* __restrict__ bias, const float* __restrict__ R,
    float* __restrict__ C, int Mm, int Nn, int Kk)
{
    __shared__ float As[BKT_G][BMT];
    __shared__ float Bs[BKT_G][BNT];

    const int tid = threadIdx.x;
    const int m0 = blockIdx.y * BMT;
    const int n0 = blockIdx.x * BNT;
    const int ty = tid >> 4, tx = tid & 15;
    const int row0 = ty * 8, col0 = tx * 8;

    float acc[8][8];
#pragma unroll
    for (int i = 0; i < 8; i++)
#pragma unroll
        for (int j = 0; j < 8; j++) acc[i][j] = 0.f;

    for (int k0 = 0; k0 < Kk; k0 += BKT_G) {
#pragma unroll
        for (int i = 0; i < 2; i++) {
            int idx = tid + i * 256;      // 0..511 float4 slots
            int r   = idx >> 2;           // 128 rows, 4 float4 per row
            int c4  = idx & 3;
            float4 va = *reinterpret_cast<const float4*>(
                &A[(size_t)(m0 + r) * Kk + k0 + c4 * 4]);
            As[c4 * 4 + 0][r] = va.x; As[c4 * 4 + 1][r] = va.y;
            As[c4 * 4 + 2][r] = va.z; As[c4 * 4 + 3][r] = va.w;
            float4 vb = *reinterpret_cast<const float4*>(
                &W[(size_t)(n0 + r) * Kk + k0 + c4 * 4]);
            Bs[c4 * 4 + 0][r] = vb.x; Bs[c4 * 4 + 1][r] = vb.y;
            Bs[c4 * 4 + 2][r] = vb.z; Bs[c4 * 4 + 3][r] = vb.w;
        }
        __syncthreads();

#pragma unroll
        for (int kk = 0; kk < BKT_G; kk++) {
            float a[8], b[8];
            *reinterpret_cast<float4*>(&a[0]) = *reinterpret_cast<const float4*>(&As[kk][row0]);
            *reinterpret_cast<float4*>(&a[4]) = *reinterpret_cast<const float4*>(&As[kk][row0 + 4]);
            *reinterpret_cast<float4*>(&b[0]) = *reinterpret_cast<const float4*>(&Bs[kk][col0]);
            *reinterpret_cast<float4*>(&b[4]) = *reinterpret_cast<const float4*>(&Bs[kk][col0 + 4]);
#pragma unroll
            for (int i = 0; i < 8; i++)
#pragma unroll
                for (int j = 0; j < 8; j++) acc[i][j] = fmaf(a[i], b[j], acc[i][j]);
        }
        __syncthreads();
    }

#pragma unroll
    for (int i = 0; i < 8; i++) {
        const size_t gr = (size_t)(m0 + row0 + i);
#pragma unroll
        for (int j = 0; j < 8; j++) {
            int gc = n0 + col0 + j;
            float val = acc[i][j] + bias[gc];
            if (RES) val += R[gr * Nn + gc];
            C[gr * Nn + gc] = val;
        }
    }
}

// ---------------------------------------------------------------------------
// Flash attention with static mask.
// Grid: (S/64, H, B). 256 threads. Q tile 64, key tile 32. fp32.
// ---------------------------------------------------------------------------
constexpr int BQ  = 64;
constexpr int BKT = 32;

__global__ __launch_bounds__(256) void attn_kernel(
    const float* __restrict__ qkv, const unsigned char* __restrict__ mask,
    float* __restrict__ ctx)
{
    __shared__ float Qs[BQ][65];
    __shared__ float Ks[BKT][65];
    __shared__ float Vs[BKT][65];
    __shared__ float Ss[BQ][BKT + 1];
    __shared__ unsigned char Msk[BQ][BKT];
    __shared__ float Mst[BQ], Lst[BQ], Crow[BQ];
    __shared__ float red[BQ][4];

    const int tid = threadIdx.x;
    const int q0 = blockIdx.x * BQ;
    const int h  = blockIdx.y;
    const int b  = blockIdx.z;

    const size_t base = (size_t)b * S * (3 * E);
    const float* Qg = qkv + base + (size_t)h * DH;
    const float* Kg = qkv + base + E + (size_t)h * DH;
    const float* Vg = qkv + base + 2 * E + (size_t)h * DH;

    // Load Q tile: 64 rows x 64 floats = 1024 float4
#pragma unroll
    for (int i = 0; i < 4; i++) {
        int idx = tid + i * 256;
        int r = idx >> 4;
        int f = idx & 15;
        float4 v = *reinterpret_cast<const float4*>(&Qg[(size_t)(q0 + r) * (3 * E) + f * 4]);
        Qs[r][f * 4 + 0] = v.x; Qs[r][f * 4 + 1] = v.y;
        Qs[r][f * 4 + 2] = v.z; Qs[r][f * 4 + 3] = v.w;
    }
    if (tid < BQ) { Mst[tid] = -3.0e38f; Lst[tid] = 0.f; }

    const int ty = tid >> 4, tx = tid & 15;
    float acc[4][4];
#pragma unroll
    for (int i = 0; i < 4; i++)
#pragma unroll
        for (int j = 0; j < 4; j++) acc[i][j] = 0.f;

    __syncthreads();

    for (int k0 = 0; k0 < S; k0 += BKT) {
        // Load K,V tiles (32 x 64 each = 512 float4 each)
#pragma unroll
        for (int i = 0; i < 2; i++) {
            int idx = tid + i * 256;
            int r = idx >> 4;
            int f = idx & 15;
            float4 kv = *reinterpret_cast<const float4*>(&Kg[(size_t)(k0 + r) * (3 * E) + f * 4]);
            Ks[r][f * 4 + 0] = kv.x; Ks[r][f * 4 + 1] = kv.y;
            Ks[r][f * 4 + 2] = kv.z; Ks[r][f * 4 + 3] = kv.w;
            float4 vv = *reinterpret_cast<const float4*>(&Vg[(size_t)(k0 + r) * (3 * E) + f * 4]);
            Vs[r][f * 4 + 0] = vv.x; Vs[r][f * 4 + 1] = vv.y;
            Vs[r][f * 4 + 2] = vv.z; Vs[r][f * 4 + 3] = vv.w;
        }
        // Mask tile: 64 x 32 bytes, 8 bytes/thread
        {
            int r = tid >> 2, seg = tid & 3;
            *reinterpret_cast<uint2*>(&Msk[r][seg * 8]) =
                *reinterpret_cast<const uint2*>(&mask[(size_t)(q0 + r) * S + k0 + seg * 8]);
        }
        __syncthreads();

        // Scores: thread handles rows ty*4..+4, cols tx*2..+2
        float sv[4][2];
#pragma unroll
        for (int i = 0; i < 4; i++)
#pragma unroll
            for (int j = 0; j < 2; j++) sv[i][j] = 0.f;
#pragma unroll 16
        for (int d = 0; d < DH; d++) {
            float a0 = Qs[ty * 4 + 0][d], a1 = Qs[ty * 4 + 1][d];
            float a2 = Qs[ty * 4 + 2][d], a3 = Qs[ty * 4 + 3][d];
            float b0 = Ks[tx * 2 + 0][d], b1 = Ks[tx * 2 + 1][d];
            sv[0][0] = fmaf(a0, b0, sv[0][0]); sv[0][1] = fmaf(a0, b1, sv[0][1]);
            sv[1][0] = fmaf(a1, b0, sv[1][0]); sv[1][1] = fmaf(a1, b1, sv[1][1]);
            sv[2][0] = fmaf(a2, b0, sv[2][0]); sv[2][1] = fmaf(a2, b1, sv[2][1]);
            sv[3][0] = fmaf(a3, b0, sv[3][0]); sv[3][1] = fmaf(a3, b1, sv[3][1]);
        }
#pragma unroll
        for (int i = 0; i < 4; i++)
#pragma unroll
            for (int j = 0; j < 2; j++) {
                int r = ty * 4 + i, c = tx * 2 + j;
                Ss[r][c] = Msk[r][c] ? sv[i][j] * SCALE : -1e9f;
            }
        __syncthreads();

        // Row max (partial, 4 threads per row)
        {
            int r = tid >> 2, part = tid & 3;
            float m = -3.0e38f;
#pragma unroll
            for (int c = part * 8; c < part * 8 + 8; c++) m = fmaxf(m, Ss[r][c]);
            red[r][part] = m;
        }
        __syncthreads();
        if (tid < BQ) {
            float mt = fmaxf(fmaxf(red[tid][0], red[tid][1]),
                             fmaxf(red[tid][2], red[tid][3]));
            float mo = Mst[tid];
            float mn = fmaxf(mo, mt);
            Mst[tid]  = mn;
            Crow[tid] = expf(mo - mn);
        }
        __syncthreads();

        // Exponentiate + partial sums
        {
            int r = tid >> 2, part = tid & 3;
            float mn = Mst[r];
            float ssum = 0.f;
#pragma unroll
            for (int c = part * 8; c < part * 8 + 8; c++) {
                float p = expf(Ss[r][c] - mn);
                Ss[r][c] = p;
                ssum += p;
            }
            red[r][part] = ssum;
        }
        __syncthreads();
        if (tid < BQ) {
            Lst[tid] = Lst[tid] * Crow[tid]
                     + red[tid][0] + red[tid][1] + red[tid][2] + red[tid][3];
        }

        // O update: rows ty*4..+4, dims tx*4..+4
#pragma unroll
        for (int i = 0; i < 4; i++) {
            float c = Crow[ty * 4 + i];
#pragma unroll
            for (int j = 0; j < 4; j++) acc[i][j] *= c;
        }
#pragma unroll 8
        for (int c = 0; c < BKT; c++) {
            float a0 = Ss[ty * 4 + 0][c], a1 = Ss[ty * 4 + 1][c];
            float a2 = Ss[ty * 4 + 2][c], a3 = Ss[ty * 4 + 3][c];
            float b0 = Vs[c][tx * 4 + 0], b1 = Vs[c][tx * 4 + 1];
            float b2 = Vs[c][tx * 4 + 2], b3 = Vs[c][tx * 4 + 3];
            acc[0][0] = fmaf(a0, b0, acc[0][0]); acc[0][1] = fmaf(a0, b1, acc[0][1]);
            acc[0][2] = fmaf(a0, b2, acc[0][2]); acc[0][3] = fmaf(a0, b3, acc[0][3]);
            acc[1][0] = fmaf(a1, b0, acc[1][0]); acc[1][1] = fmaf(a1, b1, acc[1][1]);
            acc[1][2] = fmaf(a1, b2, acc[1][2]); acc[1][3] = fmaf(a1, b3, acc[1][3]);
            acc[2][0] = fmaf(a2, b0, acc[2][0]); acc[2][1] = fmaf(a2, b1, acc[2][1]);
            acc[2][2] = fmaf(a2, b2, acc[2][2]); acc[2][3] = fmaf(a2, b3, acc[2][3]);
            acc[3][0] = fmaf(a3, b0, acc[3][0]); acc[3][1] = fmaf(a3, b1, acc[3][1]);
            acc[3][2] = fmaf(a3, b2, acc[3][2]); acc[3][3] = fmaf(a3, b3, acc[3][3]);
        }
        __syncthreads();
    }

    // Write context
#pragma unroll
    for (int i = 0; i < 4; i++) {
        int r = ty * 4 + i;
        float inv = 1.f / Lst[r];
        size_t rowbase = ((size_t)b * S + q0 + r) * E + h * DH + tx * 4;
#pragma unroll
        for (int j = 0; j < 4; j++) ctx[rowbase + j] = acc[i][j] * inv;
    }
}

// ---------------------------------------------------------------------------
// Launch
// ---------------------------------------------------------------------------
extern "C" void kernel_launch(void* const* d_in, const int* in_sizes, int n_in,
                              void* d_out, int out_size)
{
    const float*         x      = (const float*)d_in[0];
    const unsigned char* mraw   = (const unsigned char*)d_in[1];
    const float*         w_qkv  = (const float*)d_in[2];
    const float*         b_qkv  = (const float*)d_in[3];
    const float*         w_out  = (const float*)d_in[4];
    const float*         b_out  = (const float*)d_in[5];
    const float*         g1     = (const float*)d_in[6];
    const float*         beta1  = (const float*)d_in[7];
    const float*         g2     = (const float*)d_in[8];
    const float*         beta2  = (const float*)d_in[9];
    const float*         w1     = (const float*)d_in[10];
    const float*         bias1  = (const float*)d_in[11];
    const float*         w2     = (const float*)d_in[12];
    const float*         bias2  = (const float*)d_in[13];
    float*               out    = (float*)d_out;

    float *h1, *qkv, *ctx, *att, *h2, *m1;
    unsigned char* msk;
    cudaGetSymbolAddress((void**)&h1,  g_h1);
    cudaGetSymbolAddress((void**)&qkv, g_qkv);
    cudaGetSymbolAddress((void**)&ctx, g_ctx);
    cudaGetSymbolAddress((void**)&att, g_att);
    cudaGetSymbolAddress((void**)&h2,  g_h2);
    cudaGetSymbolAddress((void**)&m1,  g_m1);
    cudaGetSymbolAddress((void**)&msk, g_mask);

    // 0. Mask dtype detection + canonicalization to uint8
    mask_detect_kernel<<<1, 32>>>(mraw);
    mask_convert_kernel<<<(S * S) / 256, 256>>>(mraw, msk);

    // 1. LN1
    ln_kernel<<<M, 256>>>(x, g1, beta1, h1);

    // 2. QKV projection: [4096,1024] x [3072,1024]^T
    gemm_kernel<false><<<dim3(3 * E / BNT, M / BMT), 256>>>(
        h1, w_qkv, b_qkv, nullptr, qkv, M, 3 * E, E);

    // 3. Sparse flash attention
    attn_kernel<<<dim3(S / BQ, H, B), 256>>>(qkv, msk, ctx);

    // 4. Out projection + residual x
    gemm_kernel<true><<<dim3(E / BNT, M / BMT), 256>>>(
        ctx, w_out, b_out, x, att, M, E, E);

    // 5. LN2
    ln_kernel<<<M, 256>>>(att, g2, beta2, h2);

    // 6. MLP linear1 (no activation)
    gemm_kernel<false><<<dim3(MLP / BNT, M / BMT), 256>>>(
        h2, w1, bias1, nullptr, m1, M, MLP, E);

    // 7. MLP linear2 + residual x -> output
    gemm_kernel<true><<<dim3(E / BNT, M / BMT), 256>>>(
        m1, w2, bias2, x, out, M, E, MLP);
}

// round 4
// speedup vs baseline: 1.4691x; 1.4691x over previous
#include <cuda_runtime.h>
#include <cuda_bf16.h>
#include <math.h>
#include <stdint.h>

// Problem constants
constexpr int B   = 2;
constexpr int S   = 2048;
constexpr int E   = 1024;
constexpr int H   = 16;
constexpr int DH  = 64;
constexpr int MLP = 4096;
constexpr int M   = B * S;       // 4096 rows
constexpr float SCALE = 0.125f;  // 1/sqrt(64)

// ---------------------------------------------------------------------------
// Scratch buffers
// ---------------------------------------------------------------------------
__device__ float g_h1 [M * E];
__device__ float g_qkv[M * 3 * E];
__device__ float g_ctx[M * E];
__device__ float g_att[M * E];
__device__ float g_h2 [M * E];
__device__ float g_m1 [M * MLP];
__device__ unsigned char g_mask[S * S];
__device__ int g_mask_sz;

// ---------------------------------------------------------------------------
// Mask dtype detection + canonicalization (known-good)
// ---------------------------------------------------------------------------
__global__ void mask_detect_kernel(const unsigned char* __restrict__ m)
{
    if (threadIdx.x == 0 && blockIdx.x == 0) {
        bool is1 = false, is2 = false;
        for (int p = 0; p < 8192; p++) {
            unsigned char v = m[p];
            if (v == 1u    && (p & 3) != 0) is1 = true;
            if (v == 0x3Fu && (p & 3) == 1) is2 = true;
        }
        g_mask_sz = is1 ? 1 : (is2 ? 2 : 4);
    }
}

__global__ __launch_bounds__(256) void mask_convert_kernel(
    const unsigned char* __restrict__ m, unsigned char* __restrict__ out)
{
    const int idx = blockIdx.x * 256 + threadIdx.x;
    const int sz = g_mask_sz;
    unsigned char nz = 0;
    const unsigned char* p = m + (size_t)idx * sz;
    for (int i = 0; i < sz; i++) nz |= p[i];
    out[idx] = nz ? 1 : 0;
}

// ---------------------------------------------------------------------------
// LayerNorm (known-good)
// ---------------------------------------------------------------------------
__global__ __launch_bounds__(256) void ln_kernel(
    const float* __restrict__ in, const float* __restrict__ g,
    const float* __restrict__ beta, float* __restrict__ out)
{
    __shared__ float sred[256];
    const int tid = threadIdx.x;
    const size_t row = blockIdx.x;
    const float* x = in + row * E;

    float v[4];
    float s = 0.f;
#pragma unroll
    for (int i = 0; i < 4; i++) { v[i] = x[tid + i * 256]; s += v[i]; }

    sred[tid] = s; __syncthreads();
#pragma unroll
    for (int off = 128; off > 0; off >>= 1) {
        if (tid < off) sred[tid] += sred[tid + off];
        __syncthreads();
    }
    const float mu = sred[0] * (1.f / E);
    __syncthreads();

    float sq = 0.f;
#pragma unroll
    for (int i = 0; i < 4; i++) { float d = v[i] - mu; sq += d * d; }
    sred[tid] = sq; __syncthreads();
#pragma unroll
    for (int off = 128; off > 0; off >>= 1) {
        if (tid < off) sred[tid] += sred[tid + off];
        __syncthreads();
    }
    const float rstd = rsqrtf(sred[0] * (1.f / E) + 1e-5f);

#pragma unroll
    for (int i = 0; i < 4; i++) {
        int c = tid + i * 256;
        out[row * E + c] = (v[i] - mu) * rstd * g[c] + beta[c];
    }
}

// ---------------------------------------------------------------------------
// tf32 mma.sync GEMM: C[M,N] = A[M,K] * W[N,K]^T + bias (+ residual)
// Block tile 128x128x32, 256 threads (8 warps, 2m x 4n), warp tile 64x32.
// Smem stores operands in mma-fragment-permuted layout:
//   A_perm[mi'(8)][ks(4)][lane(32)][reg(4)]  (16KB)
//   B_perm[ni'(16)][ks(4)][lane(32)][reg(2)] (16KB)
// Double buffered => 64KB dynamic smem.
// fp32 bits fed directly as tf32 (HW truncates mantissa).
// ---------------------------------------------------------------------------
constexpr int GEMM_SMEM_DYN = 64 * 1024;

__device__ __forceinline__ void mma_tf32(float* d, const uint4& a, const uint2& b)
{
    asm volatile(
        "mma.sync.aligned.m16n8k8.row.col.f32.tf32.tf32.f32 "
        "{%0,%1,%2,%3}, {%4,%5,%6,%7}, {%8,%9}, {%0,%1,%2,%3};"
        : "+f"(d[0]), "+f"(d[1]), "+f"(d[2]), "+f"(d[3])
        : "r"(a.x), "r"(a.y), "r"(a.z), "r"(a.w), "r"(b.x), "r"(b.y));
}

template <bool RES>
__global__ __launch_bounds__(256) void gemm_mma(
    const float* __restrict__ A, const float* __restrict__ W,
    const float* __restrict__ bias, const float* __restrict__ R,
    float* __restrict__ C, int Mm, int Nn, int Kk)
{
    extern __shared__ float smem[];
    float* sA[2] = { smem,         smem + 8192  };   // 4096 floats each
    float* sB[2] = { smem + 4096,  smem + 12288 };

    const int tid  = threadIdx.x;
    const int lane = tid & 31;
    const int wid  = tid >> 5;
    const int wm   = wid >> 2;   // 0..1
    const int wn   = wid & 3;    // 0..3
    const int m0 = blockIdx.y * 128;
    const int n0 = blockIdx.x * 128;

    // loader indices (per thread, 4 float4 slots per operand tile)
    // idx = tid + j*256 ; r = idx>>3 (row 0..127) ; c4 = idx&7 (float4 within 32 cols)
    float4 Ar[4], Br[4];

    auto ldg_tile = [&](int kt) {
        const int k0 = kt << 5;
#pragma unroll
        for (int j = 0; j < 4; j++) {
            int idx = tid + j * 256;
            int r = idx >> 3, c4 = idx & 7;
            Ar[j] = *reinterpret_cast<const float4*>(&A[(size_t)(m0 + r) * Kk + k0 + c4 * 4]);
            Br[j] = *reinterpret_cast<const float4*>(&W[(size_t)(n0 + r) * Kk + k0 + c4 * 4]);
        }
    };

    auto sts_tile = [&](int bsel) {
        float* a = sA[bsel];
        float* b = sB[bsel];
#pragma unroll
        for (int j = 0; j < 4; j++) {
            int idx = tid + j * 256;
            int r = idx >> 3, c4 = idx & 7;
            // A: reg = ((c4&1)<<1) | ((r>>3)&1); kstep = c4>>1; mi' = r>>4
            {
                int reg  = ((c4 & 1) << 1) | ((r >> 3) & 1);
                int base = ((((r >> 4) * 4 + (c4 >> 1)) * 32 + ((r & 7) << 2)) << 2) + reg;
                a[base + 0] = Ar[j].x;
                a[base + 4] = Ar[j].y;
                a[base + 8] = Ar[j].z;
                a[base + 12] = Ar[j].w;
            }
            // B: reg = c4&1; kstep = c4>>1; ni' = r>>3   (r is n here)
            {
                int reg  = c4 & 1;
                int base = ((((r >> 3) * 4 + (c4 >> 1)) * 32 + ((r & 7) << 2)) << 1) + reg;
                b[base + 0] = Br[j].x;
                b[base + 2] = Br[j].y;
                b[base + 4] = Br[j].z;
                b[base + 6] = Br[j].w;
            }
        }
    };

    float acc[4][4][4];
#pragma unroll
    for (int mi = 0; mi < 4; mi++)
#pragma unroll
        for (int ni = 0; ni < 4; ni++)
#pragma unroll
            for (int q = 0; q < 4; q++) acc[mi][ni][q] = 0.f;

    const int T = Kk >> 5;

    ldg_tile(0);
    sts_tile(0);
    __syncthreads();

    for (int t = 0; t < T; t++) {
        const int cur = t & 1;
        if (t + 1 < T) ldg_tile(t + 1);

        const float* a = sA[cur];
        const float* b = sB[cur];
#pragma unroll
        for (int ks = 0; ks < 4; ks++) {
            uint4 af[4];
            uint2 bf[4];
#pragma unroll
            for (int mi = 0; mi < 4; mi++)
                af[mi] = *reinterpret_cast<const uint4*>(
                    &a[((((wm * 4 + mi) * 4 + ks) * 32 + lane) << 2)]);
#pragma unroll
            for (int ni = 0; ni < 4; ni++)
                bf[ni] = *reinterpret_cast<const uint2*>(
                    &b[((((wn * 4 + ni) * 4 + ks) * 32 + lane) << 1)]);
#pragma unroll
            for (int mi = 0; mi < 4; mi++)
#pragma unroll
                for (int ni = 0; ni < 4; ni++)
                    mma_tf32(acc[mi][ni], af[mi], bf[ni]);
        }
        __syncthreads();
        if (t + 1 < T) {
            sts_tile(1 - cur);
            __syncthreads();
        }
    }

    // Epilogue: c0:(row, col) c1:(row, col+1) c2:(row+8, col) c3:(row+8, col+1)
    const int rbase = m0 + wm * 64 + (lane >> 2);
    const int cbase = n0 + wn * 32 + (lane & 3) * 2;
#pragma unroll
    for (int mi = 0; mi < 4; mi++) {
#pragma unroll
        for (int ni = 0; ni < 4; ni++) {
            const int col = cbase + ni * 8;
            const float2 bv = *reinterpret_cast<const float2*>(&bias[col]);
#pragma unroll
            for (int half = 0; half < 2; half++) {
                const size_t row = (size_t)(rbase + mi * 16 + half * 8);
                float2 o;
                o.x = acc[mi][ni][half * 2 + 0] + bv.x;
                o.y = acc[mi][ni][half * 2 + 1] + bv.y;
                if (RES) {
                    float2 rv = *reinterpret_cast<const float2*>(&R[row * Nn + col]);
                    o.x += rv.x; o.y += rv.y;
                }
                *reinterpret_cast<float2*>(&C[row * Nn + col]) = o;
            }
        }
    }
}

// ---------------------------------------------------------------------------
// Flash attention with static mask (known-good)
// ---------------------------------------------------------------------------
constexpr int BQ  = 64;
constexpr int BKT = 32;

__global__ __launch_bounds__(256) void attn_kernel(
    const float* __restrict__ qkv, const unsigned char* __restrict__ mask,
    float* __restrict__ ctx)
{
    __shared__ float Qs[BQ][65];
    __shared__ float Ks[BKT][65];
    __shared__ float Vs[BKT][65];
    __shared__ float Ss[BQ][BKT + 1];
    __shared__ unsigned char Msk[BQ][BKT];
    __shared__ float Mst[BQ], Lst[BQ], Crow[BQ];
    __shared__ float red[BQ][4];

    const int tid = threadIdx.x;
    const int q0 = blockIdx.x * BQ;
    const int h  = blockIdx.y;
    const int b  = blockIdx.z;

    const size_t base = (size_t)b * S * (3 * E);
    const float* Qg = qkv + base + (size_t)h * DH;
    const float* Kg = qkv + base + E + (size_t)h * DH;
    const float* Vg = qkv + base + 2 * E + (size_t)h * DH;

#pragma unroll
    for (int i = 0; i < 4; i++) {
        int idx = tid + i * 256;
        int r = idx >> 4;
        int f = idx & 15;
        float4 v = *reinterpret_cast<const float4*>(&Qg[(size_t)(q0 + r) * (3 * E) + f * 4]);
        Qs[r][f * 4 + 0] = v.x; Qs[r][f * 4 + 1] = v.y;
        Qs[r][f * 4 + 2] = v.z; Qs[r][f * 4 + 3] = v.w;
    }
    if (tid < BQ) { Mst[tid] = -3.0e38f; Lst[tid] = 0.f; }

    const int ty = tid >> 4, tx = tid & 15;
    float acc[4][4];
#pragma unroll
    for (int i = 0; i < 4; i++)
#pragma unroll
        for (int j = 0; j < 4; j++) acc[i][j] = 0.f;

    __syncthreads();

    for (int k0 = 0; k0 < S; k0 += BKT) {
#pragma unroll
        for (int i = 0; i < 2; i++) {
            int idx = tid + i * 256;
            int r = idx >> 4;
            int f = idx & 15;
            float4 kv = *reinterpret_cast<const float4*>(&Kg[(size_t)(k0 + r) * (3 * E) + f * 4]);
            Ks[r][f * 4 + 0] = kv.x; Ks[r][f * 4 + 1] = kv.y;
            Ks[r][f * 4 + 2] = kv.z; Ks[r][f * 4 + 3] = kv.w;
            float4 vv = *reinterpret_cast<const float4*>(&Vg[(size_t)(k0 + r) * (3 * E) + f * 4]);
            Vs[r][f * 4 + 0] = vv.x; Vs[r][f * 4 + 1] = vv.y;
            Vs[r][f * 4 + 2] = vv.z; Vs[r][f * 4 + 3] = vv.w;
        }
        {
            int r = tid >> 2, seg = tid & 3;
            *reinterpret_cast<uint2*>(&Msk[r][seg * 8]) =
                *reinterpret_cast<const uint2*>(&mask[(size_t)(q0 + r) * S + k0 + seg * 8]);
        }
        __syncthreads();

        float sv[4][2];
#pragma unroll
        for (int i = 0; i < 4; i++)
#pragma unroll
            for (int j = 0; j < 2; j++) sv[i][j] = 0.f;
#pragma unroll 16
        for (int d = 0; d < DH; d++) {
            float a0 = Qs[ty * 4 + 0][d], a1 = Qs[ty * 4 + 1][d];
            float a2 = Qs[ty * 4 + 2][d], a3 = Qs[ty * 4 + 3][d];
            float b0 = Ks[tx * 2 + 0][d], b1 = Ks[tx * 2 + 1][d];
            sv[0][0] = fmaf(a0, b0, sv[0][0]); sv[0][1] = fmaf(a0, b1, sv[0][1]);
            sv[1][0] = fmaf(a1, b0, sv[1][0]); sv[1][1] = fmaf(a1, b1, sv[1][1]);
            sv[2][0] = fmaf(a2, b0, sv[2][0]); sv[2][1] = fmaf(a2, b1, sv[2][1]);
            sv[3][0] = fmaf(a3, b0, sv[3][0]); sv[3][1] = fmaf(a3, b1, sv[3][1]);
        }
#pragma unroll
        for (int i = 0; i < 4; i++)
#pragma unroll
            for (int j = 0; j < 2; j++) {
                int r = ty * 4 + i, c = tx * 2 + j;
                Ss[r][c] = Msk[r][c] ? sv[i][j] * SCALE : -1e9f;
            }
        __syncthreads();

        {
            int r = tid >> 2, part = tid & 3;
            float m = -3.0e38f;
#pragma unroll
            for (int c = part * 8; c < part * 8 + 8; c++) m = fmaxf(m, Ss[r][c]);
            red[r][part] = m;
        }
        __syncthreads();
        if (tid < BQ) {
            float mt = fmaxf(fmaxf(red[tid][0], red[tid][1]),
                             fmaxf(red[tid][2], red[tid][3]));
            float mo = Mst[tid];
            float mn = fmaxf(mo, mt);
            Mst[tid]  = mn;
            Crow[tid] = expf(mo - mn);
        }
        __syncthreads();

        {
            int r = tid >> 2, part = tid & 3;
            float mn = Mst[r];
            float ssum = 0.f;
#pragma unroll
            for (int c = part * 8; c < part * 8 + 8; c++) {
                float p = expf(Ss[r][c] - mn);
                Ss[r][c] = p;
                ssum += p;
            }
            red[r][part] = ssum;
        }
        __syncthreads();
        if (tid < BQ) {
            Lst[tid] = Lst[tid] * Crow[tid]
                     + red[tid][0] + red[tid][1] + red[tid][2] + red[tid][3];
        }

#pragma unroll
        for (int i = 0; i < 4; i++) {
            float c = Crow[ty * 4 + i];
#pragma unroll
            for (int j = 0; j < 4; j++) acc[i][j] *= c;
        }
#pragma unroll 8
        for (int c = 0; c < BKT; c++) {
            float a0 = Ss[ty * 4 + 0][c], a1 = Ss[ty * 4 + 1][c];
            float a2 = Ss[ty * 4 + 2][c], a3 = Ss[ty * 4 + 3][c];
            float b0 = Vs[c][tx * 4 + 0], b1 = Vs[c][tx * 4 + 1];
            float b2 = Vs[c][tx * 4 + 2], b3 = Vs[c][tx * 4 + 3];
            acc[0][0] = fmaf(a0, b0, acc[0][0]); acc[0][1] = fmaf(a0, b1, acc[0][1]);
            acc[0][2] = fmaf(a0, b2, acc[0][2]); acc[0][3] = fmaf(a0, b3, acc[0][3]);
            acc[1][0] = fmaf(a1, b0, acc[1][0]); acc[1][1] = fmaf(a1, b1, acc[1][1]);
            acc[1][2] = fmaf(a1, b2, acc[1][2]); acc[1][3] = fmaf(a1, b3, acc[1][3]);
            acc[2][0] = fmaf(a2, b0, acc[2][0]); acc[2][1] = fmaf(a2, b1, acc[2][1]);
            acc[2][2] = fmaf(a2, b2, acc[2][2]); acc[2][3] = fmaf(a2, b3, acc[2][3]);
            acc[3][0] = fmaf(a3, b0, acc[3][0]); acc[3][1] = fmaf(a3, b1, acc[3][1]);
            acc[3][2] = fmaf(a3, b2, acc[3][2]); acc[3][3] = fmaf(a3, b3, acc[3][3]);
        }
        __syncthreads();
    }

#pragma unroll
    for (int i = 0; i < 4; i++) {
        int r = ty * 4 + i;
        float inv = 1.f / Lst[r];
        size_t rowbase = ((size_t)b * S + q0 + r) * E + h * DH + tx * 4;
#pragma unroll
        for (int j = 0; j < 4; j++) ctx[rowbase + j] = acc[i][j] * inv;
    }
}

// ---------------------------------------------------------------------------
// Launch
// ---------------------------------------------------------------------------
extern "C" void kernel_launch(void* const* d_in, const int* in_sizes, int n_in,
                              void* d_out, int out_size)
{
    const float*         x      = (const float*)d_in[0];
    const unsigned char* mraw   = (const unsigned char*)d_in[1];
    const float*         w_qkv  = (const float*)d_in[2];
    const float*         b_qkv  = (const float*)d_in[3];
    const float*         w_out  = (const float*)d_in[4];
    const float*         b_out  = (const float*)d_in[5];
    const float*         g1     = (const float*)d_in[6];
    const float*         beta1  = (const float*)d_in[7];
    const float*         g2     = (const float*)d_in[8];
    const float*         beta2  = (const float*)d_in[9];
    const float*         w1     = (const float*)d_in[10];
    const float*         bias1  = (const float*)d_in[11];
    const float*         w2     = (const float*)d_in[12];
    const float*         bias2  = (const float*)d_in[13];
    float*               out    = (float*)d_out;

    float *h1, *qkv, *ctx, *att, *h2, *m1;
    unsigned char* msk;
    cudaGetSymbolAddress((void**)&h1,  g_h1);
    cudaGetSymbolAddress((void**)&qkv, g_qkv);
    cudaGetSymbolAddress((void**)&ctx, g_ctx);
    cudaGetSymbolAddress((void**)&att, g_att);
    cudaGetSymbolAddress((void**)&h2,  g_h2);
    cudaGetSymbolAddress((void**)&m1,  g_m1);
    cudaGetSymbolAddress((void**)&msk, g_mask);

    cudaFuncSetAttribute(gemm_mma<false>,
        cudaFuncAttributeMaxDynamicSharedMemorySize, GEMM_SMEM_DYN);
    cudaFuncSetAttribute(gemm_mma<true>,
        cudaFuncAttributeMaxDynamicSharedMemorySize, GEMM_SMEM_DYN);

    // 0. Mask canonicalization
    mask_detect_kernel<<<1, 32>>>(mraw);
    mask_convert_kernel<<<(S * S) / 256, 256>>>(mraw, msk);

    // 1. LN1
    ln_kernel<<<M, 256>>>(x, g1, beta1, h1);

    // 2. QKV projection
    gemm_mma<false><<<dim3(3 * E / 128, M / 128), 256, GEMM_SMEM_DYN>>>(
        h1, w_qkv, b_qkv, nullptr, qkv, M, 3 * E, E);

    // 3. Sparse flash attention
    attn_kernel<<<dim3(S / BQ, H, B), 256>>>(qkv, msk, ctx);

    // 4. Out projection + residual x
    gemm_mma<true><<<dim3(E / 128, M / 128), 256, GEMM_SMEM_DYN>>>(
        ctx, w_out, b_out, x, att, M, E, E);

    // 5. LN2
    ln_kernel<<<M, 256>>>(att, g2, beta2, h2);

    // 6. MLP linear1
    gemm_mma<false><<<dim3(MLP / 128, M / 128), 256, GEMM_SMEM_DYN>>>(
        h2, w1, bias1, nullptr, m1, M, MLP, E);

    // 7. MLP linear2 + residual x -> output
    gemm_mma<true><<<dim3(E / 128, M / 128), 256, GEMM_SMEM_DYN>>>(
        m1, w2, bias2, x, out, M, E, MLP);
}

// round 5
// speedup vs baseline: 2.7091x; 1.8441x over previous
#include <cuda_runtime.h>
#include <cuda_bf16.h>
#include <math.h>
#include <stdint.h>

// Problem constants
constexpr int B   = 2;
constexpr int S   = 2048;
constexpr int E   = 1024;
constexpr int H   = 16;
constexpr int DH  = 64;
constexpr int MLP = 4096;
constexpr int M   = B * S;       // 4096 rows
constexpr float SCALE = 0.125f;  // 1/sqrt(64)
constexpr int NBR  = S / 8;      // 256 block-rows (VEC = 8)
constexpr int CAP  = 512;        // max active columns per block-row (mean ~213, 22-sigma safe)

// ---------------------------------------------------------------------------
// Scratch buffers
// ---------------------------------------------------------------------------
__device__ float g_h1 [M * E];
__device__ float g_qkv[M * 3 * E];
__device__ float g_ctx[M * E];
__device__ float g_att[M * E];
__device__ float g_h2 [M * E];
__device__ float g_m1 [M * MLP];
__device__ unsigned char g_mask[S * S];
__device__ int g_mask_sz;
__device__ int           g_idx [NBR * CAP];   // active column indices per block-row
__device__ unsigned char g_bits[NBR * CAP];   // per-column 8-bit row mask
__device__ int           g_nact[NBR];

// ---------------------------------------------------------------------------
// Mask dtype detection + canonicalization (known-good)
// ---------------------------------------------------------------------------
__global__ void mask_detect_kernel(const unsigned char* __restrict__ m)
{
    if (threadIdx.x == 0 && blockIdx.x == 0) {
        bool is1 = false, is2 = false;
        for (int p = 0; p < 8192; p++) {
            unsigned char v = m[p];
            if (v == 1u    && (p & 3) != 0) is1 = true;
            if (v == 0x3Fu && (p & 3) == 1) is2 = true;
        }
        g_mask_sz = is1 ? 1 : (is2 ? 2 : 4);
    }
}

__global__ __launch_bounds__(256) void mask_convert_kernel(
    const unsigned char* __restrict__ m, unsigned char* __restrict__ out)
{
    const int idx = blockIdx.x * 256 + threadIdx.x;
    const int sz = g_mask_sz;
    unsigned char nz = 0;
    const unsigned char* p = m + (size_t)idx * sz;
    for (int i = 0; i < sz; i++) nz |= p[i];
    out[idx] = nz ? 1 : 0;
}

// ---------------------------------------------------------------------------
// Build per-block-row active-column lists (deterministic prefix-scan compaction)
// grid = NBR, block = 256. Each thread owns 8 consecutive columns.
// ---------------------------------------------------------------------------
__global__ __launch_bounds__(256) void build_idx_kernel(
    const unsigned char* __restrict__ mask,
    int* __restrict__ idx, unsigned char* __restrict__ bits, int* __restrict__ nact)
{
    __shared__ unsigned char tb[S];
    __shared__ int cnt[256];

    const int t  = threadIdx.x;
    const int br = blockIdx.x;

    int local = 0;
#pragma unroll
    for (int j = 0; j < 8; j++) {
        int c = t * 8 + j;
        unsigned char bt = 0;
#pragma unroll
        for (int r = 0; r < 8; r++)
            bt |= (mask[(size_t)(br * 8 + r) * S + c] ? 1u : 0u) << r;
        tb[c] = bt;
        local += (bt != 0);
    }
    cnt[t] = local;
    __syncthreads();

    if (t == 0) {
        int run = 0;
        for (int i = 0; i < 256; i++) { int v = cnt[i]; cnt[i] = run; run += v; }
        nact[br] = run < CAP ? run : CAP;
    }
    __syncthreads();

    int pos = cnt[t];
#pragma unroll
    for (int j = 0; j < 8; j++) {
        int c = t * 8 + j;
        if (tb[c] && pos < CAP) {
            idx [br * CAP + pos] = c;
            bits[br * CAP + pos] = tb[c];
            pos++;
        }
    }
}

// ---------------------------------------------------------------------------
// LayerNorm (known-good)
// ---------------------------------------------------------------------------
__global__ __launch_bounds__(256) void ln_kernel(
    const float* __restrict__ in, const float* __restrict__ g,
    const float* __restrict__ beta, float* __restrict__ out)
{
    __shared__ float sred[256];
    const int tid = threadIdx.x;
    const size_t row = blockIdx.x;
    const float* x = in + row * E;

    float v[4];
    float s = 0.f;
#pragma unroll
    for (int i = 0; i < 4; i++) { v[i] = x[tid + i * 256]; s += v[i]; }

    sred[tid] = s; __syncthreads();
#pragma unroll
    for (int off = 128; off > 0; off >>= 1) {
        if (tid < off) sred[tid] += sred[tid + off];
        __syncthreads();
    }
    const float mu = sred[0] * (1.f / E);
    __syncthreads();

    float sq = 0.f;
#pragma unroll
    for (int i = 0; i < 4; i++) { float d = v[i] - mu; sq += d * d; }
    sred[tid] = sq; __syncthreads();
#pragma unroll
    for (int off = 128; off > 0; off >>= 1) {
        if (tid < off) sred[tid] += sred[tid + off];
        __syncthreads();
    }
    const float rstd = rsqrtf(sred[0] * (1.f / E) + 1e-5f);

#pragma unroll
    for (int i = 0; i < 4; i++) {
        int c = tid + i * 256;
        out[row * E + c] = (v[i] - mu) * rstd * g[c] + beta[c];
    }
}

// ---------------------------------------------------------------------------
// bf16 split-3 mma.sync GEMM: C[M,N] = A[M,K] * W[N,K]^T + bias (+ residual)
// fp32 x = hi(bf16) + lo(bf16);  D = Ah*Bh + Ah*Bl + Al*Bh  (error ~2^-17)
// Block 128x128x32, 512 threads (16 warps, 4m x 4n), warp tile 32x32,
// m16n8k16 fragments staged pre-permuted + pre-split in smem, double buffered.
// Smem/stage: Ah,Al,Bh,Bl = 4 x 8KB = 32KB; 2 stages = 64KB dynamic.
// ---------------------------------------------------------------------------
constexpr int GEMM_SMEM_DYN = 64 * 1024;

__device__ __forceinline__ void mma_bf16(float* d, const uint4& a, const uint2& b)
{
    asm volatile(
        "mma.sync.aligned.m16n8k16.row.col.f32.bf16.bf16.f32 "
        "{%0,%1,%2,%3}, {%4,%5,%6,%7}, {%8,%9}, {%0,%1,%2,%3};"
        : "+f"(d[0]), "+f"(d[1]), "+f"(d[2]), "+f"(d[3])
        : "r"(a.x), "r"(a.y), "r"(a.z), "r"(a.w), "r"(b.x), "r"(b.y));
}

__device__ __forceinline__ void split2(float f0, float f1, uint32_t& hi, uint32_t& lo)
{
    __nv_bfloat162 h = __float22bfloat162_rn(make_float2(f0, f1));
    float2 hf = __bfloat1622float2(h);
    __nv_bfloat162 l = __float22bfloat162_rn(make_float2(f0 - hf.x, f1 - hf.y));
    hi = *reinterpret_cast<uint32_t*>(&h);
    lo = *reinterpret_cast<uint32_t*>(&l);
}

template <bool RES>
__global__ __launch_bounds__(512, 1) void gemm_bf3(
    const float* __restrict__ A, const float* __restrict__ W,
    const float* __restrict__ bias, const float* __restrict__ R,
    float* __restrict__ C, int Mm, int Nn, int Kk)
{
    extern __shared__ uint32_t su[];
    // stage s at su + s*8192 : [Ah 2048][Al 2048][Bh 2048][Bl 2048]

    const int tid  = threadIdx.x;
    const int lane = tid & 31;
    const int wid  = tid >> 5;
    const int wm   = wid >> 2;   // 0..3
    const int wn   = wid & 3;    // 0..3
    const int m0 = blockIdx.y * 128;
    const int n0 = blockIdx.x * 128;

    float4 Ar[2], Br[2];

    auto ldg_tile = [&](int kt) {
        const int k0 = kt << 5;
#pragma unroll
        for (int j = 0; j < 2; j++) {
            int idx = tid + j * 512;
            int r = idx >> 3, c4 = idx & 7;
            Ar[j] = *reinterpret_cast<const float4*>(&A[(size_t)(m0 + r) * Kk + k0 + c4 * 4]);
            Br[j] = *reinterpret_cast<const float4*>(&W[(size_t)(n0 + r) * Kk + k0 + c4 * 4]);
        }
    };

    auto sts_tile = [&](int stage) {
        uint32_t* sAh = su + stage * 8192;
        uint32_t* sAl = sAh + 2048;
        uint32_t* sBh = sAh + 4096;
        uint32_t* sBl = sAh + 6144;
#pragma unroll
        for (int j = 0; j < 2; j++) {
            int idx = tid + j * 512;
            int r = idx >> 3, c4 = idx & 7;
            float av[4] = { Ar[j].x, Ar[j].y, Ar[j].z, Ar[j].w };
            float bv[4] = { Br[j].x, Br[j].y, Br[j].z, Br[j].w };
#pragma unroll
            for (int p = 0; p < 2; p++) {
                int k0 = c4 * 4 + 2 * p;
                int ks = k0 >> 4, kl = k0 & 15;
                int lane_s = ((r & 7) << 2) | ((kl >> 1) & 3);
                uint32_t hi, lo;
                // A element
                {
                    int reg = ((kl >> 3) << 1) | ((r >> 3) & 1);
                    int pos = ((((r >> 4) * 2 + ks) * 32 + lane_s) << 2) + reg;
                    split2(av[2 * p], av[2 * p + 1], hi, lo);
                    sAh[pos] = hi; sAl[pos] = lo;
                }
                // B element
                {
                    int reg = kl >> 3;
                    int pos = ((((r >> 3) * 2 + ks) * 32 + lane_s) << 1) + reg;
                    split2(bv[2 * p], bv[2 * p + 1], hi, lo);
                    sBh[pos] = hi; sBl[pos] = lo;
                }
            }
        }
    };

    float acc[2][4][4];
#pragma unroll
    for (int mi = 0; mi < 2; mi++)
#pragma unroll
        for (int ni = 0; ni < 4; ni++)
#pragma unroll
            for (int q = 0; q < 4; q++) acc[mi][ni][q] = 0.f;

    const int T = Kk >> 5;

    ldg_tile(0);
    sts_tile(0);
    __syncthreads();

    for (int t = 0; t < T; t++) {
        const int cur = t & 1;
        if (t + 1 < T) ldg_tile(t + 1);

        const uint32_t* sAh = su + cur * 8192;
        const uint32_t* sAl = sAh + 2048;
        const uint32_t* sBh = sAh + 4096;
        const uint32_t* sBl = sAh + 6144;
#pragma unroll
        for (int ks = 0; ks < 2; ks++) {
            uint4 ah[2], al[2];
            uint2 bh[4], bl[4];
#pragma unroll
            for (int mi = 0; mi < 2; mi++) {
                int off = ((((wm * 2 + mi) * 2 + ks) * 32 + lane) << 2);
                ah[mi] = *reinterpret_cast<const uint4*>(&sAh[off]);
                al[mi] = *reinterpret_cast<const uint4*>(&sAl[off]);
            }
#pragma unroll
            for (int ni = 0; ni < 4; ni++) {
                int off = ((((wn * 4 + ni) * 2 + ks) * 32 + lane) << 1);
                bh[ni] = *reinterpret_cast<const uint2*>(&sBh[off]);
                bl[ni] = *reinterpret_cast<const uint2*>(&sBl[off]);
            }
#pragma unroll
            for (int mi = 0; mi < 2; mi++)
#pragma unroll
                for (int ni = 0; ni < 4; ni++) mma_bf16(acc[mi][ni], ah[mi], bh[ni]);
#pragma unroll
            for (int mi = 0; mi < 2; mi++)
#pragma unroll
                for (int ni = 0; ni < 4; ni++) mma_bf16(acc[mi][ni], ah[mi], bl[ni]);
#pragma unroll
            for (int mi = 0; mi < 2; mi++)
#pragma unroll
                for (int ni = 0; ni < 4; ni++) mma_bf16(acc[mi][ni], al[mi], bh[ni]);
        }
        if (t + 1 < T) sts_tile(1 - cur);
        __syncthreads();
    }

    // Epilogue (m16n8 C layout: c0/c1 row, c2/c3 row+8)
    const int rbase = m0 + wm * 32 + (lane >> 2);
    const int cbase = n0 + wn * 32 + (lane & 3) * 2;
#pragma unroll
    for (int mi = 0; mi < 2; mi++) {
#pragma unroll
        for (int ni = 0; ni < 4; ni++) {
            const int col = cbase + ni * 8;
            const float2 bv = *reinterpret_cast<const float2*>(&bias[col]);
#pragma unroll
            for (int half = 0; half < 2; half++) {
                const size_t row = (size_t)(rbase + mi * 16 + half * 8);
                float2 o;
                o.x = acc[mi][ni][half * 2 + 0] + bv.x;
                o.y = acc[mi][ni][half * 2 + 1] + bv.y;
                if (RES) {
                    float2 rv = *reinterpret_cast<const float2*>(&R[row * Nn + col]);
                    o.x += rv.x; o.y += rv.y;
                }
                *reinterpret_cast<float2*>(&C[row * Nn + col]) = o;
            }
        }
    }
}

// ---------------------------------------------------------------------------
// Block-sparse attention. Grid (NBR, H, B), 256 threads.
// Exact fp32: only active (mask=1) columns enter the softmax.
// ---------------------------------------------------------------------------
__global__ __launch_bounds__(256) void attn_sparse_kernel(
    const float* __restrict__ qkv,
    const int* __restrict__ idx_g, const unsigned char* __restrict__ bits_g,
    const int* __restrict__ nact_g, float* __restrict__ ctx)
{
    __shared__ float Qs[8][64];
    __shared__ float Ss[8][CAP];
    __shared__ int sidx[CAP];
    __shared__ unsigned char sbits[CAP];

    const int tid = threadIdx.x;
    const int br = blockIdx.x;
    const int h  = blockIdx.y;
    const int b  = blockIdx.z;
    const int q0 = br * 8;
    const int n  = nact_g[br];

    for (int i = tid; i < CAP; i += 256) {
        sidx[i]  = idx_g[br * CAP + i];
        sbits[i] = bits_g[br * CAP + i];
    }

    const size_t base = (size_t)b * S * (3 * E);
    const float* Qbase = qkv + base + (size_t)q0 * (3 * E) + h * DH;
    const float* Kbase = qkv + base + E + h * DH;
    const float* Vbase = qkv + base + 2 * E + h * DH;

    // Load Q block (8 x 64)
    {
        int r = tid >> 5;
        int c = (tid & 31) * 2;
        *reinterpret_cast<float2*>(&Qs[r][c]) =
            *reinterpret_cast<const float2*>(Qbase + (size_t)r * (3 * E) + c);
    }
    __syncthreads();

    // Phase A: scores for active columns (thread per column slot)
    for (int s = tid; s < n; s += 256) {
        const float4* kr = reinterpret_cast<const float4*>(Kbase + (size_t)sidx[s] * (3 * E));
        float a[8];
#pragma unroll
        for (int r = 0; r < 8; r++) a[r] = 0.f;
#pragma unroll 4
        for (int d4 = 0; d4 < 16; d4++) {
            float4 kv = kr[d4];
#pragma unroll
            for (int r = 0; r < 8; r++) {
                float4 qv = reinterpret_cast<const float4*>(&Qs[r][0])[d4];
                a[r] = fmaf(kv.x, qv.x, a[r]);
                a[r] = fmaf(kv.y, qv.y, a[r]);
                a[r] = fmaf(kv.z, qv.z, a[r]);
                a[r] = fmaf(kv.w, qv.w, a[r]);
            }
        }
        unsigned bt = sbits[s];
#pragma unroll
        for (int r = 0; r < 8; r++)
            Ss[r][s] = ((bt >> r) & 1) ? a[r] * SCALE : -1e9f;
    }
    __syncthreads();

    // Phase B: per-row softmax (warp w owns row w)
    const int w = tid >> 5, l = tid & 31;
    float mx = -3.0e38f;
    for (int s = l; s < n; s += 32) mx = fmaxf(mx, Ss[w][s]);
#pragma unroll
    for (int o = 16; o; o >>= 1) mx = fmaxf(mx, __shfl_xor_sync(0xFFFFFFFFu, mx, o));
    float sm = 0.f;
    for (int s = l; s < n; s += 32) {
        float p = __expf(Ss[w][s] - mx);
        Ss[w][s] = p;
        sm += p;
    }
#pragma unroll
    for (int o = 16; o; o >>= 1) sm += __shfl_xor_sync(0xFFFFFFFFu, sm, o);
    const float inv = 1.f / sm;
    __syncwarp();

    // Phase C: PV (warp w owns output row w; lane l owns dims 2l, 2l+1)
    float ax = 0.f, ay = 0.f;
    int s = 0;
    for (; s + 4 <= n; s += 4) {
#pragma unroll
        for (int u = 0; u < 4; u++) {
            float p = Ss[w][s + u];
            const float2 v = *reinterpret_cast<const float2*>(
                Vbase + (size_t)sidx[s + u] * (3 * E) + 2 * l);
            ax = fmaf(p, v.x, ax);
            ay = fmaf(p, v.y, ay);
        }
    }
    for (; s < n; s++) {
        float p = Ss[w][s];
        const float2 v = *reinterpret_cast<const float2*>(
            Vbase + (size_t)sidx[s] * (3 * E) + 2 * l);
        ax = fmaf(p, v.x, ax);
        ay = fmaf(p, v.y, ay);
    }
    *reinterpret_cast<float2*>(&ctx[((size_t)b * S + q0 + w) * E + h * DH + 2 * l]) =
        make_float2(ax * inv, ay * inv);
}

// ---------------------------------------------------------------------------
// Launch
// ---------------------------------------------------------------------------
extern "C" void kernel_launch(void* const* d_in, const int* in_sizes, int n_in,
                              void* d_out, int out_size)
{
    const float*         x      = (const float*)d_in[0];
    const unsigned char* mraw   = (const unsigned char*)d_in[1];
    const float*         w_qkv  = (const float*)d_in[2];
    const float*         b_qkv  = (const float*)d_in[3];
    const float*         w_out  = (const float*)d_in[4];
    const float*         b_out  = (const float*)d_in[5];
    const float*         g1     = (const float*)d_in[6];
    const float*         beta1  = (const float*)d_in[7];
    const float*         g2     = (const float*)d_in[8];
    const float*         beta2  = (const float*)d_in[9];
    const float*         w1     = (const float*)d_in[10];
    const float*         bias1  = (const float*)d_in[11];
    const float*         w2     = (const float*)d_in[12];
    const float*         bias2  = (const float*)d_in[13];
    float*               out    = (float*)d_out;

    float *h1, *qkv, *ctx, *att, *h2, *m1;
    unsigned char *msk, *bits;
    int *idx, *nact;
    cudaGetSymbolAddress((void**)&h1,   g_h1);
    cudaGetSymbolAddress((void**)&qkv,  g_qkv);
    cudaGetSymbolAddress((void**)&ctx,  g_ctx);
    cudaGetSymbolAddress((void**)&att,  g_att);
    cudaGetSymbolAddress((void**)&h2,   g_h2);
    cudaGetSymbolAddress((void**)&m1,   g_m1);
    cudaGetSymbolAddress((void**)&msk,  g_mask);
    cudaGetSymbolAddress((void**)&idx,  g_idx);
    cudaGetSymbolAddress((void**)&bits, g_bits);
    cudaGetSymbolAddress((void**)&nact, g_nact);

    cudaFuncSetAttribute(gemm_bf3<false>,
        cudaFuncAttributeMaxDynamicSharedMemorySize, GEMM_SMEM_DYN);
    cudaFuncSetAttribute(gemm_bf3<true>,
        cudaFuncAttributeMaxDynamicSharedMemorySize, GEMM_SMEM_DYN);

    // 0. Mask canonicalization + sparsity index build
    mask_detect_kernel<<<1, 32>>>(mraw);
    mask_convert_kernel<<<(S * S) / 256, 256>>>(mraw, msk);
    build_idx_kernel<<<NBR, 256>>>(msk, idx, bits, nact);

    // 1. LN1
    ln_kernel<<<M, 256>>>(x, g1, beta1, h1);

    // 2. QKV projection
    gemm_bf3<false><<<dim3(3 * E / 128, M / 128), 512, GEMM_SMEM_DYN>>>(
        h1, w_qkv, b_qkv, nullptr, qkv, M, 3 * E, E);

    // 3. Block-sparse attention (exact fp32)
    attn_sparse_kernel<<<dim3(NBR, H, B), 256>>>(qkv, idx, bits, nact, ctx);

    // 4. Out projection + residual x
    gemm_bf3<true><<<dim3(E / 128, M / 128), 512, GEMM_SMEM_DYN>>>(
        ctx, w_out, b_out, x, att, M, E, E);

    // 5. LN2
    ln_kernel<<<M, 256>>>(att, g2, beta2, h2);

    // 6. MLP linear1
    gemm_bf3<false><<<dim3(MLP / 128, M / 128), 512, GEMM_SMEM_DYN>>>(
        h2, w1, bias1, nullptr, m1, M, MLP, E);

    // 7. MLP linear2 + residual x -> output
    gemm_bf3<true><<<dim3(E / 128, M / 128), 512, GEMM_SMEM_DYN>>>(
        m1, w2, bias2, x, out, M, E, MLP);
}

// round 6
// speedup vs baseline: 2.8522x; 1.0528x over previous
#include <cuda_runtime.h>
#include <cuda_bf16.h>
#include <math.h>
#include <stdint.h>

// Problem constants
constexpr int B   = 2;
constexpr int S   = 2048;
constexpr int E   = 1024;
constexpr int H   = 16;
constexpr int DH  = 64;
constexpr int MLP = 4096;
constexpr int M   = B * S;       // 4096 rows
constexpr float SCALE = 0.125f;  // 1/sqrt(64)
constexpr int NBR  = S / 8;      // 256 block-rows (VEC = 8)
constexpr int CAP  = 512;        // max active cols per block-row

// ---------------------------------------------------------------------------
// Scratch buffers (device globals)
// ---------------------------------------------------------------------------
__device__ __nv_bfloat16 g_a1h[M * E],     g_a1l[M * E];      // LN1 out (split)
__device__ __nv_bfloat16 g_w1h[3 * E * E], g_w1l[3 * E * E];  // w_qkv
__device__ __nv_bfloat16 g_w2h[E * E],     g_w2l[E * E];      // w_out
__device__ __nv_bfloat16 g_w3h[MLP * E],   g_w3l[MLP * E];    // w1
__device__ __nv_bfloat16 g_w4h[E * MLP],   g_w4l[E * MLP];    // w2
__device__ float         g_qkv[M * 3 * E];                    // QKV (fp32 for attn)
__device__ __nv_bfloat16 g_cxh[M * E],     g_cxl[M * E];      // ctx (split)
__device__ float         g_att[M * E];                        // outproj + residual
__device__ __nv_bfloat16 g_a2h[M * E],     g_a2l[M * E];      // LN2 out (split)
__device__ __nv_bfloat16 g_m1h[M * MLP],   g_m1l[M * MLP];    // MLP hidden (split)
__device__ unsigned char g_mask[S * S];
__device__ int g_mask_sz;
__device__ int           g_idx [NBR * CAP];
__device__ unsigned char g_bits[NBR * CAP];
__device__ int           g_nact[NBR];

// ---------------------------------------------------------------------------
// PTX helpers
// ---------------------------------------------------------------------------
__device__ __forceinline__ uint32_t smem_u32(const void* p) {
    uint32_t a;
    asm("{ .reg .u64 t; cvta.to.shared.u64 t, %1; cvt.u32.u64 %0, t; }"
        : "=r"(a) : "l"(p));
    return a;
}
__device__ __forceinline__ void cp_async16(uint32_t saddr, const void* gptr) {
    asm volatile("cp.async.cg.shared.global [%0], [%1], 16;"
                 :: "r"(saddr), "l"(__cvta_generic_to_global(gptr)) : "memory");
}
#define CP_COMMIT() asm volatile("cp.async.commit_group;" ::: "memory")
#define CP_WAIT(n)  asm volatile("cp.async.wait_group %0;" :: "n"(n) : "memory")

__device__ __forceinline__ uint4 ldmx4(uint32_t a) {
    uint4 r;
    asm volatile("ldmatrix.sync.aligned.m8n8.x4.shared.b16 {%0,%1,%2,%3}, [%4];"
                 : "=r"(r.x), "=r"(r.y), "=r"(r.z), "=r"(r.w) : "r"(a));
    return r;
}
__device__ __forceinline__ void mma_bf16(float* d, const uint4& a, uint32_t b0, uint32_t b1)
{
    asm volatile(
        "mma.sync.aligned.m16n8k16.row.col.f32.bf16.bf16.f32 "
        "{%0,%1,%2,%3}, {%4,%5,%6,%7}, {%8,%9}, {%0,%1,%2,%3};"
        : "+f"(d[0]), "+f"(d[1]), "+f"(d[2]), "+f"(d[3])
        : "r"(a.x), "r"(a.y), "r"(a.z), "r"(a.w), "r"(b0), "r"(b1));
}
__device__ __forceinline__ void split2(float f0, float f1, uint32_t& hi, uint32_t& lo)
{
    __nv_bfloat162 h = __float22bfloat162_rn(make_float2(f0, f1));
    float2 hf = __bfloat1622float2(h);
    __nv_bfloat162 l = __float22bfloat162_rn(make_float2(f0 - hf.x, f1 - hf.y));
    hi = *reinterpret_cast<uint32_t*>(&h);
    lo = *reinterpret_cast<uint32_t*>(&l);
}

// ---------------------------------------------------------------------------
// Mask dtype detection + canonicalization (known-good)
// ---------------------------------------------------------------------------
__global__ void mask_detect_kernel(const unsigned char* __restrict__ m)
{
    if (threadIdx.x == 0 && blockIdx.x == 0) {
        bool is1 = false, is2 = false;
        for (int p = 0; p < 8192; p++) {
            unsigned char v = m[p];
            if (v == 1u    && (p & 3) != 0) is1 = true;
            if (v == 0x3Fu && (p & 3) == 1) is2 = true;
        }
        g_mask_sz = is1 ? 1 : (is2 ? 2 : 4);
    }
}

__global__ __launch_bounds__(256) void mask_convert_kernel(
    const unsigned char* __restrict__ m, unsigned char* __restrict__ out)
{
    const int idx = blockIdx.x * 256 + threadIdx.x;
    const int sz = g_mask_sz;
    unsigned char nz = 0;
    const unsigned char* p = m + (size_t)idx * sz;
    for (int i = 0; i < sz; i++) nz |= p[i];
    out[idx] = nz ? 1 : 0;
}

// ---------------------------------------------------------------------------
// Build per-block-row active-column lists (known-good)
// ---------------------------------------------------------------------------
__global__ __launch_bounds__(256) void build_idx_kernel(
    const unsigned char* __restrict__ mask,
    int* __restrict__ idx, unsigned char* __restrict__ bits, int* __restrict__ nact)
{
    __shared__ unsigned char tb[S];
    __shared__ int cnt[256];

    const int t  = threadIdx.x;
    const int br = blockIdx.x;

    int local = 0;
#pragma unroll
    for (int j = 0; j < 8; j++) {
        int c = t * 8 + j;
        unsigned char bt = 0;
#pragma unroll
        for (int r = 0; r < 8; r++)
            bt |= (mask[(size_t)(br * 8 + r) * S + c] ? 1u : 0u) << r;
        tb[c] = bt;
        local += (bt != 0);
    }
    cnt[t] = local;
    __syncthreads();

    if (t == 0) {
        int run = 0;
        for (int i = 0; i < 256; i++) { int v = cnt[i]; cnt[i] = run; run += v; }
        nact[br] = run < CAP ? run : CAP;
    }
    __syncthreads();

    int pos = cnt[t];
#pragma unroll
    for (int j = 0; j < 8; j++) {
        int c = t * 8 + j;
        if (tb[c] && pos < CAP) {
            idx [br * CAP + pos] = c;
            bits[br * CAP + pos] = tb[c];
            pos++;
        }
    }
}

// ---------------------------------------------------------------------------
// Weight split: fp32 -> bf16 hi/lo. One float4 per thread.
// ---------------------------------------------------------------------------
__global__ __launch_bounds__(256) void conv_split_kernel(
    const float* __restrict__ in,
    __nv_bfloat16* __restrict__ hi, __nv_bfloat16* __restrict__ lo)
{
    const int i = blockIdx.x * 256 + threadIdx.x;   // float4 index
    float4 v = reinterpret_cast<const float4*>(in)[i];
    uint32_t h0, l0, h1, l1;
    split2(v.x, v.y, h0, l0);
    split2(v.z, v.w, h1, l1);
    reinterpret_cast<uint2*>(hi)[i] = make_uint2(h0, h1);
    reinterpret_cast<uint2*>(lo)[i] = make_uint2(l0, l1);
}

// ---------------------------------------------------------------------------
// LayerNorm emitting bf16 hi/lo split
// ---------------------------------------------------------------------------
__global__ __launch_bounds__(256) void ln_split_kernel(
    const float* __restrict__ in, const float* __restrict__ g,
    const float* __restrict__ beta,
    __nv_bfloat16* __restrict__ oh, __nv_bfloat16* __restrict__ ol)
{
    __shared__ float sred[256];
    const int tid = threadIdx.x;
    const size_t row = blockIdx.x;
    const float* x = in + row * E;

    float v[4];
    float s = 0.f;
#pragma unroll
    for (int i = 0; i < 4; i++) { v[i] = x[tid + i * 256]; s += v[i]; }

    sred[tid] = s; __syncthreads();
#pragma unroll
    for (int off = 128; off > 0; off >>= 1) {
        if (tid < off) sred[tid] += sred[tid + off];
        __syncthreads();
    }
    const float mu = sred[0] * (1.f / E);
    __syncthreads();

    float sq = 0.f;
#pragma unroll
    for (int i = 0; i < 4; i++) { float d = v[i] - mu; sq += d * d; }
    sred[tid] = sq; __syncthreads();
#pragma unroll
    for (int off = 128; off > 0; off >>= 1) {
        if (tid < off) sred[tid] += sred[tid + off];
        __syncthreads();
    }
    const float rstd = rsqrtf(sred[0] * (1.f / E) + 1e-5f);

#pragma unroll
    for (int i = 0; i < 4; i++) {
        int c = tid + i * 256;
        float y = (v[i] - mu) * rstd * g[c] + beta[c];
        __nv_bfloat16 hb = __float2bfloat16(y);
        oh[row * E + c] = hb;
        ol[row * E + c] = __float2bfloat16(y - __bfloat162float(hb));
    }
}

// ---------------------------------------------------------------------------
// bf16 split-3 GEMM with cp.async + ldmatrix.
// C = A*W^T + bias (+R). A,W pre-split bf16 [rows, K] row-major.
// Block 128x128x32, 512 threads (16 warps 4x4), warp tile 32x32, 3 stages.
// Stage layout (32KB): [Ah 8K][Al 8K][Bh 8K][Bl 8K]; tiles 128 rows x 64B,
// 16B chunks XOR-swizzled: phys = r*4 + (c ^ ((r>>1)&3)).
// EPI: 0 = fp32, 1 = fp32 + residual, 2 = bf16 hi/lo split
// ---------------------------------------------------------------------------
constexpr int STAGES = 3;
constexpr int STAGE_BYTES = 32768;
constexpr int GEMM_SMEM = STAGES * STAGE_BYTES;   // 96KB

template <int EPI>
__global__ __launch_bounds__(512) void gemm3(
    const __nv_bfloat16* __restrict__ Ah, const __nv_bfloat16* __restrict__ Al,
    const __nv_bfloat16* __restrict__ Bh, const __nv_bfloat16* __restrict__ Bl,
    const float* __restrict__ bias, const float* __restrict__ R,
    float* __restrict__ C, __nv_bfloat16* __restrict__ Ch, __nv_bfloat16* __restrict__ Cl,
    int Nn, int Kk)
{
    extern __shared__ char smem[];
    const uint32_t sb = smem_u32(smem);

    const int tid  = threadIdx.x;
    const int lane = tid & 31;
    const int wid  = tid >> 5;
    const int wm   = wid >> 2;
    const int wn   = wid & 3;
    const int m0 = blockIdx.y * 128;
    const int n0 = blockIdx.x * 128;

    // ---- loader: thread t owns chunk t of each of 4 tiles ----
    const int lr = tid >> 2;   // row 0..127
    const int lc = tid & 3;    // logical 16B chunk
    const uint32_t sphys = (uint32_t)(lr * 4 + (lc ^ ((lr >> 1) & 3))) * 16;
    const __nv_bfloat16* gAh = Ah + (size_t)(m0 + lr) * Kk + lc * 8;
    const __nv_bfloat16* gAl = Al + (size_t)(m0 + lr) * Kk + lc * 8;
    const __nv_bfloat16* gBh = Bh + (size_t)(n0 + lr) * Kk + lc * 8;
    const __nv_bfloat16* gBl = Bl + (size_t)(n0 + lr) * Kk + lc * 8;

    auto load_stage = [&](int stage, int kt) {
        const uint32_t s0 = sb + stage * STAGE_BYTES + sphys;
        const int go = kt * 32;
        cp_async16(s0,         gAh + go);
        cp_async16(s0 + 8192,  gAl + go);
        cp_async16(s0 + 16384, gBh + go);
        cp_async16(s0 + 24576, gBl + go);
    };

    // ---- fragment address components ----
    const int arow0 = wm * 32 + (lane & 15);
    const int achb  = lane >> 4;                         // A chunk offset
    const int brow0 = wn * 32 + (lane & 7) + ((lane >> 4) << 3);
    const int bchb  = (lane >> 3) & 1;                   // B chunk offset

    float acc[2][4][4];
#pragma unroll
    for (int mi = 0; mi < 2; mi++)
#pragma unroll
        for (int ni = 0; ni < 4; ni++)
#pragma unroll
            for (int q = 0; q < 4; q++) acc[mi][ni][q] = 0.f;

    const int T = Kk >> 5;

    load_stage(0, 0); CP_COMMIT();
    load_stage(1, 1); CP_COMMIT();

    int stage = 0;
    for (int t = 0; t < T; t++) {
        if (t + 2 < T) load_stage((stage + 2) % STAGES, t + 2);
        CP_COMMIT();
        CP_WAIT(2);
        __syncthreads();

        const uint32_t base = sb + stage * STAGE_BYTES;
#pragma unroll
        for (int ks = 0; ks < 2; ks++) {
            uint4 ah[2], al[2];
#pragma unroll
            for (int mi = 0; mi < 2; mi++) {
                int row = arow0 + mi * 16;
                int c = ks * 2 + achb;
                uint32_t ad = base + (uint32_t)(row * 4 + (c ^ ((row >> 1) & 3))) * 16;
                ah[mi] = ldmx4(ad);
                al[mi] = ldmx4(ad + 8192);
            }
            uint4 bh[2], bl[2];
#pragma unroll
            for (int np = 0; np < 2; np++) {
                int row = brow0 + np * 16;
                int c = ks * 2 + bchb;
                uint32_t bd = base + 16384 + (uint32_t)(row * 4 + (c ^ ((row >> 1) & 3))) * 16;
                bh[np] = ldmx4(bd);
                bl[np] = ldmx4(bd + 8192);
            }
            uint32_t bh0[4] = { bh[0].x, bh[0].z, bh[1].x, bh[1].z };
            uint32_t bh1[4] = { bh[0].y, bh[0].w, bh[1].y, bh[1].w };
            uint32_t bl0[4] = { bl[0].x, bl[0].z, bl[1].x, bl[1].z };
            uint32_t bl1[4] = { bl[0].y, bl[0].w, bl[1].y, bl[1].w };
#pragma unroll
            for (int mi = 0; mi < 2; mi++)
#pragma unroll
                for (int ni = 0; ni < 4; ni++)
                    mma_bf16(acc[mi][ni], ah[mi], bh0[ni], bh1[ni]);
#pragma unroll
            for (int mi = 0; mi < 2; mi++)
#pragma unroll
                for (int ni = 0; ni < 4; ni++)
                    mma_bf16(acc[mi][ni], ah[mi], bl0[ni], bl1[ni]);
#pragma unroll
            for (int mi = 0; mi < 2; mi++)
#pragma unroll
                for (int ni = 0; ni < 4; ni++)
                    mma_bf16(acc[mi][ni], al[mi], bh0[ni], bh1[ni]);
        }
        __syncthreads();
        stage = (stage + 1) % STAGES;
    }

    // ---- epilogue ----
    const int rb = m0 + wm * 32 + (lane >> 2);
    const int cb = n0 + wn * 32 + (lane & 3) * 2;
#pragma unroll
    for (int mi = 0; mi < 2; mi++) {
#pragma unroll
        for (int ni = 0; ni < 4; ni++) {
            const int col = cb + ni * 8;
            const float2 bv = *reinterpret_cast<const float2*>(&bias[col]);
#pragma unroll
            for (int half = 0; half < 2; half++) {
                const size_t row = (size_t)(rb + mi * 16 + half * 8);
                float ox = acc[mi][ni][half * 2 + 0] + bv.x;
                float oy = acc[mi][ni][half * 2 + 1] + bv.y;
                if (EPI == 1) {
                    float2 rv = *reinterpret_cast<const float2*>(&R[row * Nn + col]);
                    ox += rv.x; oy += rv.y;
                }
                if (EPI == 2) {
                    uint32_t hh, ll;
                    split2(ox, oy, hh, ll);
                    *reinterpret_cast<uint32_t*>(&Ch[row * Nn + col]) = hh;
                    *reinterpret_cast<uint32_t*>(&Cl[row * Nn + col]) = ll;
                } else {
                    *reinterpret_cast<float2*>(&C[row * Nn + col]) = make_float2(ox, oy);
                }
            }
        }
    }
}

// ---------------------------------------------------------------------------
// Block-sparse attention (known-good), now emits bf16 hi/lo ctx
// ---------------------------------------------------------------------------
__global__ __launch_bounds__(256) void attn_sparse_kernel(
    const float* __restrict__ qkv,
    const int* __restrict__ idx_g, const unsigned char* __restrict__ bits_g,
    const int* __restrict__ nact_g,
    __nv_bfloat16* __restrict__ cxh, __nv_bfloat16* __restrict__ cxl)
{
    __shared__ float Qs[8][64];
    __shared__ float Ss[8][CAP];
    __shared__ int sidx[CAP];
    __shared__ unsigned char sbits[CAP];

    const int tid = threadIdx.x;
    const int br = blockIdx.x;
    const int hd = blockIdx.y;
    const int b  = blockIdx.z;
    const int q0 = br * 8;
    const int n  = nact_g[br];

    for (int i = tid; i < CAP; i += 256) {
        sidx[i]  = idx_g[br * CAP + i];
        sbits[i] = bits_g[br * CAP + i];
    }

    const size_t base = (size_t)b * S * (3 * E);
    const float* Qbase = qkv + base + (size_t)q0 * (3 * E) + hd * DH;
    const float* Kbase = qkv + base + E + hd * DH;
    const float* Vbase = qkv + base + 2 * E + hd * DH;

    {
        int r = tid >> 5;
        int c = (tid & 31) * 2;
        *reinterpret_cast<float2*>(&Qs[r][c]) =
            *reinterpret_cast<const float2*>(Qbase + (size_t)r * (3 * E) + c);
    }
    __syncthreads();

    for (int s = tid; s < n; s += 256) {
        const float4* kr = reinterpret_cast<const float4*>(Kbase + (size_t)sidx[s] * (3 * E));
        float a[8];
#pragma unroll
        for (int r = 0; r < 8; r++) a[r] = 0.f;
#pragma unroll 4
        for (int d4 = 0; d4 < 16; d4++) {
            float4 kv = kr[d4];
#pragma unroll
            for (int r = 0; r < 8; r++) {
                float4 qv = reinterpret_cast<const float4*>(&Qs[r][0])[d4];
                a[r] = fmaf(kv.x, qv.x, a[r]);
                a[r] = fmaf(kv.y, qv.y, a[r]);
                a[r] = fmaf(kv.z, qv.z, a[r]);
                a[r] = fmaf(kv.w, qv.w, a[r]);
            }
        }
        unsigned bt = sbits[s];
#pragma unroll
        for (int r = 0; r < 8; r++)
            Ss[r][s] = ((bt >> r) & 1) ? a[r] * SCALE : -1e9f;
    }
    __syncthreads();

    const int w = tid >> 5, l = tid & 31;
    float mx = -3.0e38f;
    for (int s = l; s < n; s += 32) mx = fmaxf(mx, Ss[w][s]);
#pragma unroll
    for (int o = 16; o; o >>= 1) mx = fmaxf(mx, __shfl_xor_sync(0xFFFFFFFFu, mx, o));
    float sm = 0.f;
    for (int s = l; s < n; s += 32) {
        float p = __expf(Ss[w][s] - mx);
        Ss[w][s] = p;
        sm += p;
    }
#pragma unroll
    for (int o = 16; o; o >>= 1) sm += __shfl_xor_sync(0xFFFFFFFFu, sm, o);
    const float inv = 1.f / sm;
    __syncwarp();

    float ax = 0.f, ay = 0.f;
    int s = 0;
    for (; s + 4 <= n; s += 4) {
#pragma unroll
        for (int u = 0; u < 4; u++) {
            float p = Ss[w][s + u];
            const float2 v = *reinterpret_cast<const float2*>(
                Vbase + (size_t)sidx[s + u] * (3 * E) + 2 * l);
            ax = fmaf(p, v.x, ax);
            ay = fmaf(p, v.y, ay);
        }
    }
    for (; s < n; s++) {
        float p = Ss[w][s];
        const float2 v = *reinterpret_cast<const float2*>(
            Vbase + (size_t)sidx[s] * (3 * E) + 2 * l);
        ax = fmaf(p, v.x, ax);
        ay = fmaf(p, v.y, ay);
    }
    float ox = ax * inv, oy = ay * inv;
    uint32_t hh, ll;
    split2(ox, oy, hh, ll);
    const size_t off = ((size_t)b * S + q0 + w) * E + hd * DH + 2 * l;
    *reinterpret_cast<uint32_t*>(&cxh[off]) = hh;
    *reinterpret_cast<uint32_t*>(&cxl[off]) = ll;
}

// ---------------------------------------------------------------------------
// Launch
// ---------------------------------------------------------------------------
extern "C" void kernel_launch(void* const* d_in, const int* in_sizes, int n_in,
                              void* d_out, int out_size)
{
    const float*         x      = (const float*)d_in[0];
    const unsigned char* mraw   = (const unsigned char*)d_in[1];
    const float*         w_qkv  = (const float*)d_in[2];
    const float*         b_qkv  = (const float*)d_in[3];
    const float*         w_out  = (const float*)d_in[4];
    const float*         b_out  = (const float*)d_in[5];
    const float*         g1     = (const float*)d_in[6];
    const float*         beta1  = (const float*)d_in[7];
    const float*         g2     = (const float*)d_in[8];
    const float*         beta2  = (const float*)d_in[9];
    const float*         w1     = (const float*)d_in[10];
    const float*         bias1  = (const float*)d_in[11];
    const float*         w2     = (const float*)d_in[12];
    const float*         bias2  = (const float*)d_in[13];
    float*               out    = (float*)d_out;

    __nv_bfloat16 *a1h, *a1l, *w1h, *w1l, *w2h, *w2l, *w3h, *w3l, *w4h, *w4l;
    __nv_bfloat16 *cxh, *cxl, *a2h, *a2l, *m1h, *m1l;
    float *qkv, *att;
    unsigned char *msk, *bits;
    int *idx, *nact;
    cudaGetSymbolAddress((void**)&a1h, g_a1h); cudaGetSymbolAddress((void**)&a1l, g_a1l);
    cudaGetSymbolAddress((void**)&w1h, g_w1h); cudaGetSymbolAddress((void**)&w1l, g_w1l);
    cudaGetSymbolAddress((void**)&w2h, g_w2h); cudaGetSymbolAddress((void**)&w2l, g_w2l);
    cudaGetSymbolAddress((void**)&w3h, g_w3h); cudaGetSymbolAddress((void**)&w3l, g_w3l);
    cudaGetSymbolAddress((void**)&w4h, g_w4h); cudaGetSymbolAddress((void**)&w4l, g_w4l);
    cudaGetSymbolAddress((void**)&cxh, g_cxh); cudaGetSymbolAddress((void**)&cxl, g_cxl);
    cudaGetSymbolAddress((void**)&a2h, g_a2h); cudaGetSymbolAddress((void**)&a2l, g_a2l);
    cudaGetSymbolAddress((void**)&m1h, g_m1h); cudaGetSymbolAddress((void**)&m1l, g_m1l);
    cudaGetSymbolAddress((void**)&qkv, g_qkv);
    cudaGetSymbolAddress((void**)&att, g_att);
    cudaGetSymbolAddress((void**)&msk, g_mask);
    cudaGetSymbolAddress((void**)&idx, g_idx);
    cudaGetSymbolAddress((void**)&bits, g_bits);
    cudaGetSymbolAddress((void**)&nact, g_nact);

    cudaFuncSetAttribute(gemm3<0>, cudaFuncAttributeMaxDynamicSharedMemorySize, GEMM_SMEM);
    cudaFuncSetAttribute(gemm3<1>, cudaFuncAttributeMaxDynamicSharedMemorySize, GEMM_SMEM);
    cudaFuncSetAttribute(gemm3<2>, cudaFuncAttributeMaxDynamicSharedMemorySize, GEMM_SMEM);

    // 0. Mask canonicalization + sparsity index
    mask_detect_kernel<<<1, 32>>>(mraw);
    mask_convert_kernel<<<(S * S) / 256, 256>>>(mraw, msk);
    build_idx_kernel<<<NBR, 256>>>(msk, idx, bits, nact);

    // 0b. Weight splits
    conv_split_kernel<<<3 * E * E / 1024, 256>>>(w_qkv, w1h, w1l);
    conv_split_kernel<<<E * E / 1024, 256>>>(w_out, w2h, w2l);
    conv_split_kernel<<<MLP * E / 1024, 256>>>(w1, w3h, w3l);
    conv_split_kernel<<<E * MLP / 1024, 256>>>(w2, w4h, w4l);

    // 1. LN1 -> split
    ln_split_kernel<<<M, 256>>>(x, g1, beta1, a1h, a1l);

    // 2. QKV projection (fp32 out)
    gemm3<0><<<dim3(3 * E / 128, M / 128), 512, GEMM_SMEM>>>(
        a1h, a1l, w1h, w1l, b_qkv, nullptr, qkv, nullptr, nullptr, 3 * E, E);

    // 3. Block-sparse attention -> ctx split
    attn_sparse_kernel<<<dim3(NBR, H, B), 256>>>(qkv, idx, bits, nact, cxh, cxl);

    // 4. Out projection + residual x (fp32 out)
    gemm3<1><<<dim3(E / 128, M / 128), 512, GEMM_SMEM>>>(
        cxh, cxl, w2h, w2l, b_out, x, att, nullptr, nullptr, E, E);

    // 5. LN2 -> split
    ln_split_kernel<<<M, 256>>>(att, g2, beta2, a2h, a2l);

    // 6. MLP linear1 (split out)
    gemm3<2><<<dim3(MLP / 128, M / 128), 512, GEMM_SMEM>>>(
        a2h, a2l, w3h, w3l, bias1, nullptr, nullptr, m1h, m1l, MLP, E);

    // 7. MLP linear2 + residual x -> output
    gemm3<1><<<dim3(E / 128, M / 128), 512, GEMM_SMEM>>>(
        m1h, m1l, w4h, w4l, bias2, x, out, nullptr, nullptr, E, MLP);
}